// round 1
// baseline (speedup 1.0000x reference)
#include <cuda_runtime.h>

// ============================================================================
// PAM_Module: dual axial attention (width + height) on template + scene maps.
//
// Restructured math (per map, per batch):
//   q,k = conv1x1(x)  (Cq=8 channels each)
//   attn_w[q,k] = softmax_k( sum_{cq,h} q[cq,h,q] * k[cq,h,k] )   [W,W]
//   attn_h[q,k] = softmax_k( sum_{cq,w} q[cq,q,w] * k[cq,k,w] )   [H,H]
//   U[c,h,w]   = a_w * sum_k x[c,h,k]*attn_w[w,k]  +  a_h * sum_k attn_h[h,k]*x[c,k,w]
//   out[c,h,w] = 2*x[c,h,w] + sum_c' Wv[c,c']*U[c',h,w] + (a_w+a_h)*bv[c]
// (bias-through-softmax identity: rows of attn sum to 1, so conv-v bias folds
//  into a constant; Wv factored out of both branches -> single final conv.)
// ============================================================================

#define BB 8
#define CC 64
#define CQ 8

// Scratch (reused sequentially: template pipeline first, then scene).
__device__ float g_q[4194304];    // [B, CQ, H, W]  (scene-sized)
__device__ float g_k[4194304];
__device__ float g_aw[524288];    // [B, W, W] width attention
__device__ float g_ah[524288];    // [B, H, H] height attention
__device__ float g_U[33554432];   // [B, C, H, W] combined attended map

// ----------------------------------------------------------------------------
// K1: q,k 1x1 conv. One thread per pixel. grid (npix/256, B), 256 threads.
// ----------------------------------------------------------------------------
__global__ void qk_conv_kernel(const float* __restrict__ x,
                               const float* __restrict__ qw, const float* __restrict__ qb,
                               const float* __restrict__ kw, const float* __restrict__ kb,
                               int npix)
{
    __shared__ float wq[CQ * CC], wk[CQ * CC];
    int tid = threadIdx.x;
    for (int i = tid; i < CQ * CC; i += 256) { wq[i] = qw[i]; wk[i] = kw[i]; }
    __syncthreads();

    int b = blockIdx.y;
    int p = blockIdx.x * 256 + tid;
    const float* xb = x + (size_t)b * CC * npix + p;

    float aq[CQ], ak[CQ];
#pragma unroll
    for (int i = 0; i < CQ; i++) { aq[i] = qb[i]; ak[i] = kb[i]; }

#pragma unroll 4
    for (int c = 0; c < CC; c++) {
        float xv = xb[(size_t)c * npix];
#pragma unroll
        for (int i = 0; i < CQ; i++) {
            aq[i] = fmaf(wq[i * CC + c], xv, aq[i]);
            ak[i] = fmaf(wk[i * CC + c], xv, ak[i]);
        }
    }
    size_t o = (size_t)b * CQ * npix + p;
#pragma unroll
    for (int i = 0; i < CQ; i++) {
        g_q[o + (size_t)i * npix] = aq[i];
        g_k[o + (size_t)i * npix] = ak[i];
    }
}

// ----------------------------------------------------------------------------
// K2w: width logits. C[b][i][j] = sum_{d<D} Q[d*W+i] * K[d*W+j], D = CQ*H.
// Both operands are column-contiguous (A^T * B form) -> natural [kk][i] smem.
// 64x64 tile, 4x4 microtile, 256 threads. grid (W/64, W/64, B).
// ----------------------------------------------------------------------------
__global__ void logits_w_kernel(int W, int D)
{
    __shared__ __align__(16) float As[16][64];
    __shared__ __align__(16) float Bs[16][64];
    int b = blockIdx.z;
    const float* Q = g_q + (size_t)b * D * W;
    const float* K = g_k + (size_t)b * D * W;
    int i0 = blockIdx.x * 64, j0 = blockIdx.y * 64;
    int tid = threadIdx.x, tr = tid >> 4, tc = tid & 15;
    float acc[4][4] = {};

    for (int d0 = 0; d0 < D; d0 += 16) {
#pragma unroll
        for (int l = tid; l < 1024; l += 256) {
            int kk = l >> 6, i = l & 63;
            As[kk][i] = Q[(size_t)(d0 + kk) * W + i0 + i];
            Bs[kk][i] = K[(size_t)(d0 + kk) * W + j0 + i];
        }
        __syncthreads();
#pragma unroll
        for (int kk = 0; kk < 16; kk++) {
            float4 a4 = *(const float4*)&As[kk][tr * 4];
            float4 b4 = *(const float4*)&Bs[kk][tc * 4];
            float a[4] = {a4.x, a4.y, a4.z, a4.w};
            float bb[4] = {b4.x, b4.y, b4.z, b4.w};
#pragma unroll
            for (int ti = 0; ti < 4; ti++)
#pragma unroll
                for (int tj = 0; tj < 4; tj++)
                    acc[ti][tj] = fmaf(a[ti], bb[tj], acc[ti][tj]);
        }
        __syncthreads();
    }
    size_t base = (size_t)b * W * W;
#pragma unroll
    for (int ti = 0; ti < 4; ti++)
#pragma unroll
        for (int tj = 0; tj < 4; tj++)
            g_aw[base + (size_t)(i0 + tr * 4 + ti) * W + j0 + tc * 4 + tj] = acc[ti][tj];
}

// ----------------------------------------------------------------------------
// K2h: height logits. C[b][i][j] = sum_{cq,w} q[b,cq,i,w]*k[b,cq,j,w].
// A*B^T form (both row-major over K). 64x64 tile. grid (H/64, H/64, B).
// ----------------------------------------------------------------------------
__global__ void logits_h_kernel(int H, int W)
{
    __shared__ float As[64][17];
    __shared__ float Bs[64][17];
    int b = blockIdx.z;
    int i0 = blockIdx.x * 64, j0 = blockIdx.y * 64;
    int tid = threadIdx.x, tr = tid >> 4, tc = tid & 15;
    float acc[4][4] = {};

    for (int cq = 0; cq < CQ; cq++) {
        const float* Q = g_q + ((size_t)b * CQ + cq) * H * W;
        const float* K = g_k + ((size_t)b * CQ + cq) * H * W;
        for (int w0 = 0; w0 < W; w0 += 16) {
#pragma unroll
            for (int l = tid; l < 1024; l += 256) {
                int m = l >> 4, kk = l & 15;
                As[m][kk] = Q[(size_t)(i0 + m) * W + w0 + kk];
                Bs[m][kk] = K[(size_t)(j0 + m) * W + w0 + kk];
            }
            __syncthreads();
#pragma unroll
            for (int kk = 0; kk < 16; kk++) {
                float a[4], bb[4];
#pragma unroll
                for (int t = 0; t < 4; t++) { a[t] = As[tr * 4 + t][kk]; bb[t] = Bs[tc * 4 + t][kk]; }
#pragma unroll
                for (int ti = 0; ti < 4; ti++)
#pragma unroll
                    for (int tj = 0; tj < 4; tj++)
                        acc[ti][tj] = fmaf(a[ti], bb[tj], acc[ti][tj]);
            }
            __syncthreads();
        }
    }
    size_t base = (size_t)b * H * H;
#pragma unroll
    for (int ti = 0; ti < 4; ti++)
#pragma unroll
        for (int tj = 0; tj < 4; tj++)
            g_ah[base + (size_t)(i0 + tr * 4 + ti) * H + j0 + tc * 4 + tj] = acc[ti][tj];
}

// ----------------------------------------------------------------------------
// K3: row softmax in place. grid = B*W rows, blockDim = W (64 or 256).
// ----------------------------------------------------------------------------
__global__ void softmax_kernel(int which, int W)
{
    float* a = (which ? g_ah : g_aw) + (size_t)blockIdx.x * W;
    int tid = threadIdx.x;
    __shared__ float red[256];
    float v = a[tid];
    red[tid] = v; __syncthreads();
    for (int s = blockDim.x >> 1; s > 0; s >>= 1) {
        if (tid < s) red[tid] = fmaxf(red[tid], red[tid + s]);
        __syncthreads();
    }
    float mx = red[0]; __syncthreads();
    float e = __expf(v - mx);
    red[tid] = e; __syncthreads();
    for (int s = blockDim.x >> 1; s > 0; s >>= 1) {
        if (tid < s) red[tid] += red[tid + s];
        __syncthreads();
    }
    a[tid] = e * (1.0f / red[0]);
}

// ----------------------------------------------------------------------------
// K4: width PV. U[b,m,j] = scale * sum_k X[b,m,k] * AW[b,j,k]   (A*B^T)
// M = C*H, N = W, K = W. BM x 64 tile, TM x 4 microtile, 256 threads.
// grid (M/BM, W/64, B).
// ----------------------------------------------------------------------------
template <int BM, int TM>
__global__ void yw_kernel(const float* __restrict__ x, const float* __restrict__ scale_p,
                          int M, int W)
{
    __shared__ float As[BM][17];
    __shared__ float Bs[64][17];
    int b = blockIdx.z;
    int m0 = blockIdx.x * BM, j0 = blockIdx.y * 64;
    const float* X = x + (size_t)b * M * W;
    const float* A = g_aw + (size_t)b * W * W;
    int tid = threadIdx.x, tr = tid >> 4, tc = tid & 15;
    float acc[TM][4] = {};

    for (int k0 = 0; k0 < W; k0 += 16) {
#pragma unroll
        for (int l = tid; l < BM * 16; l += 256) {
            int m = l >> 4, kk = l & 15;
            As[m][kk] = X[(size_t)(m0 + m) * W + k0 + kk];
        }
#pragma unroll
        for (int l = tid; l < 1024; l += 256) {
            int m = l >> 4, kk = l & 15;
            Bs[m][kk] = A[(size_t)(j0 + m) * W + k0 + kk];
        }
        __syncthreads();
#pragma unroll
        for (int kk = 0; kk < 16; kk++) {
            float a[TM], bb[4];
#pragma unroll
            for (int t = 0; t < TM; t++) a[t] = As[tr * TM + t][kk];
#pragma unroll
            for (int t = 0; t < 4; t++) bb[t] = Bs[tc * 4 + t][kk];
#pragma unroll
            for (int ti = 0; ti < TM; ti++)
#pragma unroll
                for (int tj = 0; tj < 4; tj++)
                    acc[ti][tj] = fmaf(a[ti], bb[tj], acc[ti][tj]);
        }
        __syncthreads();
    }
    float sc = scale_p[0];
    size_t base = (size_t)b * M * W;
#pragma unroll
    for (int ti = 0; ti < TM; ti++)
#pragma unroll
        for (int tj = 0; tj < 4; tj++)
            g_U[base + (size_t)(m0 + tr * TM + ti) * W + j0 + tc * 4 + tj] = sc * acc[ti][tj];
}

// ----------------------------------------------------------------------------
// K5: height PV, accumulated. U[b,c,i,j] += scale * sum_k AH[b,i,k]*X[b,c,k,j]
// (A*B form). Per (b,c) GEMM: M=H, N=W, K=H. grid (H/BM, W/64, B*C).
// ----------------------------------------------------------------------------
template <int BM, int TM>
__global__ void yh_kernel(const float* __restrict__ x, const float* __restrict__ scale_p,
                          int H, int W)
{
    __shared__ float As[BM][17];
    __shared__ __align__(16) float Bs[16][64];
    int z = blockIdx.z;
    int b = z >> 6, c = z & 63;
    int i0 = blockIdx.x * BM, j0 = blockIdx.y * 64;
    const float* A = g_ah + (size_t)b * H * H;
    const float* X = x + ((size_t)b * CC + c) * H * W;
    int tid = threadIdx.x, tr = tid >> 4, tc = tid & 15;
    float acc[TM][4] = {};

    for (int k0 = 0; k0 < H; k0 += 16) {
#pragma unroll
        for (int l = tid; l < BM * 16; l += 256) {
            int m = l >> 4, kk = l & 15;
            As[m][kk] = A[(size_t)(i0 + m) * H + k0 + kk];
        }
#pragma unroll
        for (int l = tid; l < 1024; l += 256) {
            int kk = l >> 6, j = l & 63;
            Bs[kk][j] = X[(size_t)(k0 + kk) * W + j0 + j];
        }
        __syncthreads();
#pragma unroll
        for (int kk = 0; kk < 16; kk++) {
            float a[TM];
#pragma unroll
            for (int t = 0; t < TM; t++) a[t] = As[tr * TM + t][kk];
            float4 b4 = *(const float4*)&Bs[kk][tc * 4];
            float bb[4] = {b4.x, b4.y, b4.z, b4.w};
#pragma unroll
            for (int ti = 0; ti < TM; ti++)
#pragma unroll
                for (int tj = 0; tj < 4; tj++)
                    acc[ti][tj] = fmaf(a[ti], bb[tj], acc[ti][tj]);
        }
        __syncthreads();
    }
    float sc = scale_p[0];
    size_t base = ((size_t)b * CC + c) * H * W;
#pragma unroll
    for (int ti = 0; ti < TM; ti++)
#pragma unroll
        for (int tj = 0; tj < 4; tj++) {
            size_t idx = base + (size_t)(i0 + tr * TM + ti) * W + j0 + tc * 4 + tj;
            g_U[idx] += sc * acc[ti][tj];
        }
}

// ----------------------------------------------------------------------------
// K6: final conv + residual. out[b,c,p] = 2x + sum_c' Wv[c,c']*U[b,c',p] + cb[c]
// M=C=64, N=64 pixels per block, K=64. grid (1, npix/64, B).
// ----------------------------------------------------------------------------
__global__ void final_kernel(const float* __restrict__ x, const float* __restrict__ vw,
                             const float* __restrict__ vb, float* __restrict__ out,
                             const float* __restrict__ sw_p, const float* __restrict__ sh_p,
                             int npix)
{
    __shared__ float As[64][17];
    __shared__ __align__(16) float Bs[16][64];
    int b = blockIdx.z;
    int p0 = blockIdx.y * 64;
    const float* Ub = g_U + (size_t)b * CC * npix;
    int tid = threadIdx.x, tr = tid >> 4, tc = tid & 15;
    float acc[4][4] = {};

    for (int k0 = 0; k0 < CC; k0 += 16) {
#pragma unroll
        for (int l = tid; l < 1024; l += 256) {
            int m = l >> 4, kk = l & 15;
            As[m][kk] = vw[m * CC + k0 + kk];
        }
#pragma unroll
        for (int l = tid; l < 1024; l += 256) {
            int kk = l >> 6, j = l & 63;
            Bs[kk][j] = Ub[(size_t)(k0 + kk) * npix + p0 + j];
        }
        __syncthreads();
#pragma unroll
        for (int kk = 0; kk < 16; kk++) {
            float a[4];
#pragma unroll
            for (int t = 0; t < 4; t++) a[t] = As[tr * 4 + t][kk];
            float4 b4 = *(const float4*)&Bs[kk][tc * 4];
            float bb[4] = {b4.x, b4.y, b4.z, b4.w};
#pragma unroll
            for (int ti = 0; ti < 4; ti++)
#pragma unroll
                for (int tj = 0; tj < 4; tj++)
                    acc[ti][tj] = fmaf(a[ti], bb[tj], acc[ti][tj]);
        }
        __syncthreads();
    }
    float cb = sw_p[0] + sh_p[0];
#pragma unroll
    for (int ti = 0; ti < 4; ti++) {
        int c = tr * 4 + ti;
        float bias = cb * vb[c];
        size_t rowo = ((size_t)b * CC + c) * npix + p0 + tc * 4;
#pragma unroll
        for (int tj = 0; tj < 4; tj++) {
            size_t idx = rowo + tj;
            out[idx] = acc[ti][tj] + 2.0f * x[idx] + bias;
        }
    }
}

// ----------------------------------------------------------------------------
// Launch: template pipeline then scene pipeline (scratch reused sequentially).
// ----------------------------------------------------------------------------
extern "C" void kernel_launch(void* const* d_in, const int* in_sizes, int n_in,
                              void* d_out, int out_size)
{
    const float* tmap  = (const float*)d_in[0];
    const float* smap  = (const float*)d_in[1];
    const float* tq_w  = (const float*)d_in[2];
    const float* tq_b  = (const float*)d_in[3];
    const float* tk_w  = (const float*)d_in[4];
    const float* tk_b  = (const float*)d_in[5];
    const float* tv_w  = (const float*)d_in[6];
    const float* tv_b  = (const float*)d_in[7];
    const float* sq_w  = (const float*)d_in[8];
    const float* sq_b  = (const float*)d_in[9];
    const float* sk_w  = (const float*)d_in[10];
    const float* sk_b  = (const float*)d_in[11];
    const float* sv_w  = (const float*)d_in[12];
    const float* sv_b  = (const float*)d_in[13];
    const float* alpha = (const float*)d_in[14];  // template width scale
    const float* beta  = (const float*)d_in[15];  // scene width scale
    const float* gamma = (const float*)d_in[16];  // template height scale
    const float* omega = (const float*)d_in[17];  // scene height scale

    float* out_t = (float*)d_out;
    float* out_s = out_t + (size_t)BB * CC * 64 * 64;

    // ---------------- template map: H = W = 64 ----------------
    {
        const int H = 64, W = 64, npix = H * W, D = CQ * H, M = CC * H;
        qk_conv_kernel<<<dim3(npix / 256, BB), 256>>>(tmap, tq_w, tq_b, tk_w, tk_b, npix);
        logits_w_kernel<<<dim3(W / 64, W / 64, BB), 256>>>(W, D);
        logits_h_kernel<<<dim3(H / 64, H / 64, BB), 256>>>(H, W);
        softmax_kernel<<<BB * W, W>>>(0, W);
        softmax_kernel<<<BB * H, H>>>(1, H);
        yw_kernel<128, 8><<<dim3(M / 128, W / 64, BB), 256>>>(tmap, alpha, M, W);
        yh_kernel<64, 4><<<dim3(H / 64, W / 64, BB * CC), 256>>>(tmap, gamma, H, W);
        final_kernel<<<dim3(1, npix / 64, BB), 256>>>(tmap, tv_w, tv_b, out_t, alpha, gamma, npix);
    }

    // ---------------- scene map: H = W = 256 ----------------
    {
        const int H = 256, W = 256, npix = H * W, D = CQ * H, M = CC * H;
        qk_conv_kernel<<<dim3(npix / 256, BB), 256>>>(smap, sq_w, sq_b, sk_w, sk_b, npix);
        logits_w_kernel<<<dim3(W / 64, W / 64, BB), 256>>>(W, D);
        logits_h_kernel<<<dim3(H / 64, H / 64, BB), 256>>>(H, W);
        softmax_kernel<<<BB * W, W>>>(0, W);
        softmax_kernel<<<BB * H, H>>>(1, H);
        yw_kernel<128, 8><<<dim3(M / 128, W / 64, BB), 256>>>(smap, beta, M, W);
        yh_kernel<128, 8><<<dim3(H / 128, W / 64, BB * CC), 256>>>(smap, omega, H, W);
        final_kernel<<<dim3(1, npix / 64, BB), 256>>>(smap, sv_w, sv_b, out_s, beta, omega, npix);
    }
}

// round 4
// speedup vs baseline: 2.9989x; 2.9989x over previous
#include <cuda_runtime.h>

// ============================================================================
// PAM_Module: dual axial attention. All GEMMs on tensor pipe via
// mma.sync.m16n8k8 tf32 (fp32 accumulate). Restructured math:
//   U = a_w * (X @ AWᵀ)  +  a_h * (AH @ X)      (per batch / per channel)
//   out = 2x + Wv @ U + (a_w+a_h)*bv
// (bias-through-softmax identity + shared-Wv factoring.)
// ============================================================================

#define BB 8
#define CC 64
#define CQ 8

__device__ float g_q[4194304];    // [B, CQ, H, W]
__device__ float g_k[4194304];
__device__ float g_aw[524288];    // [B, W, W]
__device__ float g_ah[524288];    // [B, H, H]
__device__ float g_U[33554432];   // [B, C, H, W]

__device__ __forceinline__ unsigned f2tf(float f) {
    unsigned u; asm("cvt.rna.tf32.f32 %0, %1;" : "=r"(u) : "f"(f)); return u;
}
__device__ __forceinline__ void mma8(float* c, const unsigned* a, const unsigned* b) {
    asm volatile("mma.sync.aligned.m16n8k8.row.col.f32.tf32.tf32.f32 "
        "{%0,%1,%2,%3}, {%4,%5,%6,%7}, {%8,%9}, {%0,%1,%2,%3};"
        : "+f"(c[0]), "+f"(c[1]), "+f"(c[2]), "+f"(c[3])
        : "r"(a[0]), "r"(a[1]), "r"(a[2]), "r"(a[3]), "r"(b[0]), "r"(b[1]));
}

// ----------------------------------------------------------------------------
// K1: q,k 1x1 conv (memory bound, SIMT).
// ----------------------------------------------------------------------------
__global__ void __launch_bounds__(256) qk_conv_kernel(
    const float* __restrict__ x,
    const float* __restrict__ qw, const float* __restrict__ qb,
    const float* __restrict__ kw, const float* __restrict__ kb,
    int npix)
{
    __shared__ float wq[CQ * CC], wk[CQ * CC];
    int tid = threadIdx.x;
    for (int i = tid; i < CQ * CC; i += 256) { wq[i] = qw[i]; wk[i] = kw[i]; }
    __syncthreads();

    int b = blockIdx.y;
    int p = blockIdx.x * 256 + tid;
    const float* xb = x + (size_t)b * CC * npix + p;

    float aq[CQ], ak[CQ];
#pragma unroll
    for (int i = 0; i < CQ; i++) { aq[i] = qb[i]; ak[i] = kb[i]; }

#pragma unroll 4
    for (int c = 0; c < CC; c++) {
        float xv = xb[(size_t)c * npix];
#pragma unroll
        for (int i = 0; i < CQ; i++) {
            aq[i] = fmaf(wq[i * CC + c], xv, aq[i]);
            ak[i] = fmaf(wk[i * CC + c], xv, ak[i]);
        }
    }
    size_t o = (size_t)b * CQ * npix + p;
#pragma unroll
    for (int i = 0; i < CQ; i++) {
        g_q[o + (size_t)i * npix] = aq[i];
        g_k[o + (size_t)i * npix] = ak[i];
    }
}

// ----------------------------------------------------------------------------
// K2w: width logits, C[i,j] = sum_d Q[d,i]*K[d,j].  (AᵀB)
// BM=BN=64, BK=32, 256 thr. grid (W/64, W/64, B).
// ----------------------------------------------------------------------------
__global__ void __launch_bounds__(256) logits_w_mma(int W, int D)
{
    __shared__ unsigned As[64][36];   // [m][k]
    __shared__ unsigned Bs[32][72];   // [k][n]
    int b = blockIdx.z;
    const float* Q = g_q + (size_t)b * D * W;
    const float* K = g_k + (size_t)b * D * W;
    int i0 = blockIdx.x * 64, j0 = blockIdx.y * 64;
    int tid = threadIdx.x, wid = tid >> 5, lane = tid & 31;
    int g = lane >> 2, t4 = lane & 3;
    int wm = wid >> 1, wn = wid & 1;
    float acc[4][4] = {};

    for (int d0 = 0; d0 < D; d0 += 32) {
#pragma unroll
        for (int l = tid; l < 2048; l += 256) {
            int kk = l >> 6, m = l & 63;
            As[m][kk] = f2tf(Q[(size_t)(d0 + kk) * W + i0 + m]);
        }
#pragma unroll
        for (int l = tid; l < 2048; l += 256) {
            int kk = l >> 6, n = l & 63;
            Bs[kk][n] = f2tf(K[(size_t)(d0 + kk) * W + j0 + n]);
        }
        __syncthreads();
#pragma unroll
        for (int kb = 0; kb < 32; kb += 8) {
            unsigned af[4], bf[4][2];
            int r = wm * 16 + g;
            af[0] = As[r][kb + t4];     af[1] = As[r + 8][kb + t4];
            af[2] = As[r][kb + t4 + 4]; af[3] = As[r + 8][kb + t4 + 4];
#pragma unroll
            for (int ni = 0; ni < 4; ni++) {
                int n = wn * 32 + ni * 8 + g;
                bf[ni][0] = Bs[kb + t4][n];
                bf[ni][1] = Bs[kb + t4 + 4][n];
            }
#pragma unroll
            for (int ni = 0; ni < 4; ni++) mma8(acc[ni], af, bf[ni]);
        }
        __syncthreads();
    }
    size_t base = (size_t)b * W * W;
#pragma unroll
    for (int ni = 0; ni < 4; ni++) {
        int r = i0 + wm * 16 + g;
        int cix = j0 + wn * 32 + ni * 8 + 2 * t4;
        *(float2*)&g_aw[base + (size_t)r * W + cix] = make_float2(acc[ni][0], acc[ni][1]);
        *(float2*)&g_aw[base + (size_t)(r + 8) * W + cix] = make_float2(acc[ni][2], acc[ni][3]);
    }
}

// ----------------------------------------------------------------------------
// K2h: height logits, C[i,j] = sum_{cq,w} Q[cq,i,w]*K[cq,j,w].  (ABᵀ)
// BM=BN=64, BK=32. grid (H/64, H/64, B).
// ----------------------------------------------------------------------------
__global__ void __launch_bounds__(256) logits_h_mma(int H, int W)
{
    __shared__ unsigned As[64][36];   // [m][k]
    __shared__ unsigned Bs[64][36];   // [n][k]
    int b = blockIdx.z;
    int i0 = blockIdx.x * 64, j0 = blockIdx.y * 64;
    int tid = threadIdx.x, wid = tid >> 5, lane = tid & 31;
    int g = lane >> 2, t4 = lane & 3;
    int wm = wid >> 1, wn = wid & 1;
    float acc[4][4] = {};

    for (int cq = 0; cq < CQ; cq++) {
        const float* Q = g_q + ((size_t)b * CQ + cq) * H * W;
        const float* K = g_k + ((size_t)b * CQ + cq) * H * W;
        for (int w0 = 0; w0 < W; w0 += 32) {
#pragma unroll
            for (int l = tid; l < 512; l += 256) {
                int m = l >> 3, kq = (l & 7) << 2;
                float4 va = *(const float4*)&Q[(size_t)(i0 + m) * W + w0 + kq];
                As[m][kq] = f2tf(va.x); As[m][kq+1] = f2tf(va.y);
                As[m][kq+2] = f2tf(va.z); As[m][kq+3] = f2tf(va.w);
                float4 vb = *(const float4*)&K[(size_t)(j0 + m) * W + w0 + kq];
                Bs[m][kq] = f2tf(vb.x); Bs[m][kq+1] = f2tf(vb.y);
                Bs[m][kq+2] = f2tf(vb.z); Bs[m][kq+3] = f2tf(vb.w);
            }
            __syncthreads();
#pragma unroll
            for (int kb = 0; kb < 32; kb += 8) {
                unsigned af[4], bf[4][2];
                int r = wm * 16 + g;
                af[0] = As[r][kb + t4];     af[1] = As[r + 8][kb + t4];
                af[2] = As[r][kb + t4 + 4]; af[3] = As[r + 8][kb + t4 + 4];
#pragma unroll
                for (int ni = 0; ni < 4; ni++) {
                    int n = wn * 32 + ni * 8 + g;
                    bf[ni][0] = Bs[n][kb + t4];
                    bf[ni][1] = Bs[n][kb + t4 + 4];
                }
#pragma unroll
                for (int ni = 0; ni < 4; ni++) mma8(acc[ni], af, bf[ni]);
            }
            __syncthreads();
        }
    }
    size_t base = (size_t)b * H * H;
#pragma unroll
    for (int ni = 0; ni < 4; ni++) {
        int r = i0 + wm * 16 + g;
        int cix = j0 + wn * 32 + ni * 8 + 2 * t4;
        *(float2*)&g_ah[base + (size_t)r * H + cix] = make_float2(acc[ni][0], acc[ni][1]);
        *(float2*)&g_ah[base + (size_t)(r + 8) * H + cix] = make_float2(acc[ni][2], acc[ni][3]);
    }
}

// ----------------------------------------------------------------------------
// K3: row softmax in place.
// ----------------------------------------------------------------------------
__global__ void softmax_kernel(int which, int W)
{
    float* a = (which ? g_ah : g_aw) + (size_t)blockIdx.x * W;
    int tid = threadIdx.x;
    __shared__ float red[256];
    float v = a[tid];
    red[tid] = v; __syncthreads();
    for (int s = blockDim.x >> 1; s > 0; s >>= 1) {
        if (tid < s) red[tid] = fmaxf(red[tid], red[tid + s]);
        __syncthreads();
    }
    float mx = red[0]; __syncthreads();
    float e = __expf(v - mx);
    red[tid] = e; __syncthreads();
    for (int s = blockDim.x >> 1; s > 0; s >>= 1) {
        if (tid < s) red[tid] += red[tid + s];
        __syncthreads();
    }
    a[tid] = e * (1.0f / red[0]);
}

// ----------------------------------------------------------------------------
// K4: width PV. U[b,m,j] = sc * sum_k X[m,k]*AW[j,k].  (ABᵀ)
// BM=128, BN=64, BK=32. grid (M/128, W/64, B).
// ----------------------------------------------------------------------------
__global__ void __launch_bounds__(256) yw_mma(
    const float* __restrict__ x, const float* __restrict__ scale_p, int M, int W)
{
    __shared__ unsigned As[128][36];  // [m][k]
    __shared__ unsigned Bs[64][36];   // [n][k]
    int b = blockIdx.z;
    int m0 = blockIdx.x * 128, j0 = blockIdx.y * 64;
    const float* X = x + (size_t)b * M * W;
    const float* A = g_aw + (size_t)b * W * W;
    int tid = threadIdx.x, wid = tid >> 5, lane = tid & 31;
    int g = lane >> 2, t4 = lane & 3;
    int wm = wid >> 1, wn = wid & 1;
    float acc[2][4][4] = {};

    for (int k0 = 0; k0 < W; k0 += 32) {
#pragma unroll
        for (int l = tid; l < 1024; l += 256) {
            int m = l >> 3, kq = (l & 7) << 2;
            float4 v = *(const float4*)&X[(size_t)(m0 + m) * W + k0 + kq];
            As[m][kq] = f2tf(v.x); As[m][kq+1] = f2tf(v.y);
            As[m][kq+2] = f2tf(v.z); As[m][kq+3] = f2tf(v.w);
        }
#pragma unroll
        for (int l = tid; l < 512; l += 256) {
            int n = l >> 3, kq = (l & 7) << 2;
            float4 v = *(const float4*)&A[(size_t)(j0 + n) * W + k0 + kq];
            Bs[n][kq] = f2tf(v.x); Bs[n][kq+1] = f2tf(v.y);
            Bs[n][kq+2] = f2tf(v.z); Bs[n][kq+3] = f2tf(v.w);
        }
        __syncthreads();
#pragma unroll
        for (int kb = 0; kb < 32; kb += 8) {
            unsigned af[2][4], bf[4][2];
#pragma unroll
            for (int mi = 0; mi < 2; mi++) {
                int r = wm * 32 + mi * 16 + g;
                af[mi][0] = As[r][kb + t4];     af[mi][1] = As[r + 8][kb + t4];
                af[mi][2] = As[r][kb + t4 + 4]; af[mi][3] = As[r + 8][kb + t4 + 4];
            }
#pragma unroll
            for (int ni = 0; ni < 4; ni++) {
                int n = wn * 32 + ni * 8 + g;
                bf[ni][0] = Bs[n][kb + t4];
                bf[ni][1] = Bs[n][kb + t4 + 4];
            }
#pragma unroll
            for (int mi = 0; mi < 2; mi++)
#pragma unroll
                for (int ni = 0; ni < 4; ni++)
                    mma8(acc[mi][ni], af[mi], bf[ni]);
        }
        __syncthreads();
    }
    float sc = scale_p[0];
    size_t base = (size_t)b * M * W;
#pragma unroll
    for (int mi = 0; mi < 2; mi++)
#pragma unroll
        for (int ni = 0; ni < 4; ni++) {
            int r = m0 + wm * 32 + mi * 16 + g;
            int cix = j0 + wn * 32 + ni * 8 + 2 * t4;
            *(float2*)&g_U[base + (size_t)r * W + cix] =
                make_float2(sc * acc[mi][ni][0], sc * acc[mi][ni][1]);
            *(float2*)&g_U[base + (size_t)(r + 8) * W + cix] =
                make_float2(sc * acc[mi][ni][2], sc * acc[mi][ni][3]);
        }
}

// ----------------------------------------------------------------------------
// K5: height PV, accumulated. U[b,c,i,j] += sc * sum_k AH[i,k]*X[c,k,j]. (AB)
// BM = MI*64, BN=64, BK=32. grid (H/BM, W/64, B*C).
// ----------------------------------------------------------------------------
template <int MI>
__global__ void __launch_bounds__(256) yh_mma(
    const float* __restrict__ x, const float* __restrict__ scale_p, int H, int W)
{
    __shared__ unsigned As[MI * 64][36];  // [m][k]
    __shared__ unsigned Bs[32][72];       // [k][n]
    int z = blockIdx.z, b = z >> 6, c = z & 63;
    int i0 = blockIdx.x * (MI * 64), j0 = blockIdx.y * 64;
    const float* A = g_ah + (size_t)b * H * H;
    const float* X = x + ((size_t)b * CC + c) * H * W;
    int tid = threadIdx.x, wid = tid >> 5, lane = tid & 31;
    int g = lane >> 2, t4 = lane & 3;
    int wm = wid >> 1, wn = wid & 1;
    float acc[MI][4][4] = {};

    for (int k0 = 0; k0 < H; k0 += 32) {
#pragma unroll
        for (int l = tid; l < MI * 512; l += 256) {
            int m = l >> 3, kq = (l & 7) << 2;
            float4 v = *(const float4*)&A[(size_t)(i0 + m) * H + k0 + kq];
            As[m][kq] = f2tf(v.x); As[m][kq+1] = f2tf(v.y);
            As[m][kq+2] = f2tf(v.z); As[m][kq+3] = f2tf(v.w);
        }
#pragma unroll
        for (int l = tid; l < 512; l += 256) {
            int kk = l >> 4, jq = (l & 15) << 2;
            float4 v = *(const float4*)&X[(size_t)(k0 + kk) * W + j0 + jq];
            Bs[kk][jq] = f2tf(v.x); Bs[kk][jq+1] = f2tf(v.y);
            Bs[kk][jq+2] = f2tf(v.z); Bs[kk][jq+3] = f2tf(v.w);
        }
        __syncthreads();
#pragma unroll
        for (int kb = 0; kb < 32; kb += 8) {
            unsigned af[MI][4], bf[4][2];
#pragma unroll
            for (int mi = 0; mi < MI; mi++) {
                int r = wm * (MI * 16) + mi * 16 + g;
                af[mi][0] = As[r][kb + t4];     af[mi][1] = As[r + 8][kb + t4];
                af[mi][2] = As[r][kb + t4 + 4]; af[mi][3] = As[r + 8][kb + t4 + 4];
            }
#pragma unroll
            for (int ni = 0; ni < 4; ni++) {
                int n = wn * 32 + ni * 8 + g;
                bf[ni][0] = Bs[kb + t4][n];
                bf[ni][1] = Bs[kb + t4 + 4][n];
            }
#pragma unroll
            for (int mi = 0; mi < MI; mi++)
#pragma unroll
                for (int ni = 0; ni < 4; ni++)
                    mma8(acc[mi][ni], af[mi], bf[ni]);
        }
        __syncthreads();
    }
    float sc = scale_p[0];
    size_t base = ((size_t)b * CC + c) * H * W;
#pragma unroll
    for (int mi = 0; mi < MI; mi++)
#pragma unroll
        for (int ni = 0; ni < 4; ni++) {
            int r = i0 + wm * (MI * 16) + mi * 16 + g;
            int cix = j0 + wn * 32 + ni * 8 + 2 * t4;
            float2* p0 = (float2*)&g_U[base + (size_t)r * W + cix];
            float2 v0 = *p0;
            v0.x += sc * acc[mi][ni][0]; v0.y += sc * acc[mi][ni][1];
            *p0 = v0;
            float2* p1 = (float2*)&g_U[base + (size_t)(r + 8) * W + cix];
            float2 v1 = *p1;
            v1.x += sc * acc[mi][ni][2]; v1.y += sc * acc[mi][ni][3];
            *p1 = v1;
        }
}

// ----------------------------------------------------------------------------
// K6: final conv + residual. out[c,p] = sum_k Wv[c,k]*U[k,p] + 2x + cb*vb[c]
// M=64(C), BN=64 pixels, K=64. grid (1, npix/64, B).
// ----------------------------------------------------------------------------
__global__ void __launch_bounds__(256) final_mma(
    const float* __restrict__ x, const float* __restrict__ vw,
    const float* __restrict__ vb, float* __restrict__ out,
    const float* __restrict__ sw_p, const float* __restrict__ sh_p, int npix)
{
    __shared__ unsigned As[64][36];  // [c][k]
    __shared__ unsigned Bs[32][72];  // [k][p]
    int b = blockIdx.z;
    int p0 = blockIdx.y * 64;
    const float* Ub = g_U + (size_t)b * CC * npix;
    int tid = threadIdx.x, wid = tid >> 5, lane = tid & 31;
    int g = lane >> 2, t4 = lane & 3;
    int wm = wid >> 1, wn = wid & 1;
    float acc[4][4] = {};

    for (int k0 = 0; k0 < CC; k0 += 32) {
#pragma unroll
        for (int l = tid; l < 512; l += 256) {
            int m = l >> 3, kq = (l & 7) << 2;
            float4 v = *(const float4*)&vw[m * CC + k0 + kq];
            As[m][kq] = f2tf(v.x); As[m][kq+1] = f2tf(v.y);
            As[m][kq+2] = f2tf(v.z); As[m][kq+3] = f2tf(v.w);
        }
#pragma unroll
        for (int l = tid; l < 512; l += 256) {
            int kk = l >> 4, jq = (l & 15) << 2;
            float4 v = *(const float4*)&Ub[(size_t)(k0 + kk) * npix + p0 + jq];
            Bs[kk][jq] = f2tf(v.x); Bs[kk][jq+1] = f2tf(v.y);
            Bs[kk][jq+2] = f2tf(v.z); Bs[kk][jq+3] = f2tf(v.w);
        }
        __syncthreads();
#pragma unroll
        for (int kb = 0; kb < 32; kb += 8) {
            unsigned af[4], bf[4][2];
            int r = wm * 16 + g;
            af[0] = As[r][kb + t4];     af[1] = As[r + 8][kb + t4];
            af[2] = As[r][kb + t4 + 4]; af[3] = As[r + 8][kb + t4 + 4];
#pragma unroll
            for (int ni = 0; ni < 4; ni++) {
                int n = wn * 32 + ni * 8 + g;
                bf[ni][0] = Bs[kb + t4][n];
                bf[ni][1] = Bs[kb + t4 + 4][n];
            }
#pragma unroll
            for (int ni = 0; ni < 4; ni++) mma8(acc[ni], af, bf[ni]);
        }
        __syncthreads();
    }
    float cb = sw_p[0] + sh_p[0];
    int c0 = wm * 16 + g;
    float bias0 = cb * vb[c0], bias1 = cb * vb[c0 + 8];
#pragma unroll
    for (int ni = 0; ni < 4; ni++) {
        int cix = p0 + wn * 32 + ni * 8 + 2 * t4;
        size_t i0 = ((size_t)b * CC + c0) * npix + cix;
        size_t i1 = ((size_t)b * CC + c0 + 8) * npix + cix;
        float2 x0 = *(const float2*)&x[i0];
        float2 x1 = *(const float2*)&x[i1];
        *(float2*)&out[i0] = make_float2(acc[ni][0] + 2.0f * x0.x + bias0,
                                         acc[ni][1] + 2.0f * x0.y + bias0);
        *(float2*)&out[i1] = make_float2(acc[ni][2] + 2.0f * x1.x + bias1,
                                         acc[ni][3] + 2.0f * x1.y + bias1);
    }
}

// ----------------------------------------------------------------------------
// Launch: template pipeline then scene pipeline (scratch reused sequentially).
// ----------------------------------------------------------------------------
extern "C" void kernel_launch(void* const* d_in, const int* in_sizes, int n_in,
                              void* d_out, int out_size)
{
    const float* tmap  = (const float*)d_in[0];
    const float* smap  = (const float*)d_in[1];
    const float* tq_w  = (const float*)d_in[2];
    const float* tq_b  = (const float*)d_in[3];
    const float* tk_w  = (const float*)d_in[4];
    const float* tk_b  = (const float*)d_in[5];
    const float* tv_w  = (const float*)d_in[6];
    const float* tv_b  = (const float*)d_in[7];
    const float* sq_w  = (const float*)d_in[8];
    const float* sq_b  = (const float*)d_in[9];
    const float* sk_w  = (const float*)d_in[10];
    const float* sk_b  = (const float*)d_in[11];
    const float* sv_w  = (const float*)d_in[12];
    const float* sv_b  = (const float*)d_in[13];
    const float* alpha = (const float*)d_in[14];
    const float* beta  = (const float*)d_in[15];
    const float* gamma = (const float*)d_in[16];
    const float* omega = (const float*)d_in[17];

    float* out_t = (float*)d_out;
    float* out_s = out_t + (size_t)BB * CC * 64 * 64;

    // ---------------- template map: H = W = 64 ----------------
    {
        const int H = 64, W = 64, npix = H * W, D = CQ * H, M = CC * H;
        qk_conv_kernel<<<dim3(npix / 256, BB), 256>>>(tmap, tq_w, tq_b, tk_w, tk_b, npix);
        logits_w_mma<<<dim3(W / 64, W / 64, BB), 256>>>(W, D);
        logits_h_mma<<<dim3(H / 64, H / 64, BB), 256>>>(H, W);
        softmax_kernel<<<BB * W, W>>>(0, W);
        softmax_kernel<<<BB * H, H>>>(1, H);
        yw_mma<<<dim3(M / 128, W / 64, BB), 256>>>(tmap, alpha, M, W);
        yh_mma<1><<<dim3(H / 64, W / 64, BB * CC), 256>>>(tmap, gamma, H, W);
        final_mma<<<dim3(1, npix / 64, BB), 256>>>(tmap, tv_w, tv_b, out_t, alpha, gamma, npix);
    }

    // ---------------- scene map: H = W = 256 ----------------
    {
        const int H = 256, W = 256, npix = H * W, D = CQ * H, M = CC * H;
        qk_conv_kernel<<<dim3(npix / 256, BB), 256>>>(smap, sq_w, sq_b, sk_w, sk_b, npix);
        logits_w_mma<<<dim3(W / 64, W / 64, BB), 256>>>(W, D);
        logits_h_mma<<<dim3(H / 64, H / 64, BB), 256>>>(H, W);
        softmax_kernel<<<BB * W, W>>>(0, W);
        softmax_kernel<<<BB * H, H>>>(1, H);
        yw_mma<<<dim3(M / 128, W / 64, BB), 256>>>(smap, beta, M, W);
        yh_mma<2><<<dim3(H / 128, W / 64, BB * CC), 256>>>(smap, omega, H, W);
        final_mma<<<dim3(1, npix / 64, BB), 256>>>(smap, sv_w, sv_b, out_s, beta, omega, npix);
    }
}